// round 15
// baseline (speedup 1.0000x reference)
#include <cuda_runtime.h>
#include <cuda_bf16.h>
#include <math.h>
#include <stdint.h>

typedef unsigned long long u64;
typedef uint32_t u32;

constexpr int kB = 4, kN = 1024, kNH = 8, kHID = 256;
constexpr int kROWS = kB * kN;
constexpr int kT = 2048;

// ---- attn smem layout (bytes), K/V/ck/mk double-buffered ----
constexpr int SO_CK  = 16384;              // 2 x 256
constexpr int SO_MK  = 16896;              // 2 x 256
constexpr int SO_QHI = 17408, SO_QLO = 27648;              // 10240 each
constexpr int SO_KHI = 37888, SO_KLO = 48128;              // 2 x 5120 each
constexpr int SO_VHI = 58368, SO_VLO = 68608;
constexpr int ATTN_SMEM = 78848;

// ---- packed bf16 hi/lo scratch (u32 = 2 bf16) ----
__device__ u32 g_xh  [kROWS * 128], g_xl  [kROWS * 128];   // LN output
__device__ u32 g_qkvh[kROWS * 384], g_qkvl[kROWS * 384];   // qkv (q pre-scaled)
__device__ u32 g_wqh [256 * 384],   g_wql [256 * 384];     // Wqkv
__device__ u32 g_wph [256 * 128],   g_wpl [256 * 128];     // Wproj
__device__ u32 g_aoh [kROWS * 128], g_aol [kROWS * 128];   // attention output
__device__ float g_tab[kNH * kT];                          // head-major, log2e pre-scaled

// ---------------- helpers ----------------
__device__ __forceinline__ u32 smem_u32(const void* p) {
    u32 a;
    asm("{ .reg .u64 t; cvta.to.shared.u64 t, %1; cvt.u32.u64 %0, t; }" : "=r"(a) : "l"(p));
    return a;
}
__device__ __forceinline__ void cp16(u32 dst, const void* src) {
    asm volatile("cp.async.cg.shared.global [%0], [%1], 16;" :: "r"(dst), "l"(src));
}
#define CP_COMMIT() asm volatile("cp.async.commit_group;" ::: "memory")
#define CP_WAIT(n)  asm volatile("cp.async.wait_group %0;" :: "n"(n) : "memory")
__device__ __forceinline__ void ldsm_x4(u32* r, u32 a) {
    asm volatile("ldmatrix.sync.aligned.m8n8.x4.shared.b16 {%0,%1,%2,%3}, [%4];"
        : "=r"(r[0]), "=r"(r[1]), "=r"(r[2]), "=r"(r[3]) : "r"(a));
}
__device__ __forceinline__ void ldsm_x4_t(u32* r, u32 a) {
    asm volatile("ldmatrix.sync.aligned.m8n8.x4.trans.shared.b16 {%0,%1,%2,%3}, [%4];"
        : "=r"(r[0]), "=r"(r[1]), "=r"(r[2]), "=r"(r[3]) : "r"(a));
}
__device__ __forceinline__ void mma_bf16(float* d, const u32* a, u32 b0, u32 b1) {
    asm volatile(
        "mma.sync.aligned.m16n8k16.row.col.f32.bf16.bf16.f32 "
        "{%0,%1,%2,%3}, {%4,%5,%6,%7}, {%8,%9}, {%0,%1,%2,%3};"
        : "+f"(d[0]), "+f"(d[1]), "+f"(d[2]), "+f"(d[3])
        : "r"(a[0]), "r"(a[1]), "r"(a[2]), "r"(a[3]), "r"(b0), "r"(b1));
}
__device__ __forceinline__ float ex2(float x) {
    float y; asm("ex2.approx.f32 %0, %1;" : "=f"(y) : "f"(x)); return y;
}
__device__ __forceinline__ u32 pk2(float a, float b) {
    __nv_bfloat162 t = __floats2bfloat162_rn(a, b);
    return *reinterpret_cast<u32*>(&t);
}
__device__ __forceinline__ float lo_f(u32 h) { return __uint_as_float(h << 16); }
__device__ __forceinline__ float hi_f(u32 h) { return __uint_as_float(h & 0xffff0000u); }

// ---------------- LayerNorm -> packed hi/lo ----------------
__global__ void ln_kernel(const float* __restrict__ hin, const float* __restrict__ gamma,
                          const float* __restrict__ beta)
{
    __shared__ float red[16];
    int row = blockIdx.x, t = threadIdx.x;
    float x = hin[(size_t)row * kHID + t];
    float s = x, s2 = x * x;
    #pragma unroll
    for (int off = 16; off; off >>= 1) {
        s  += __shfl_xor_sync(0xffffffffu, s,  off);
        s2 += __shfl_xor_sync(0xffffffffu, s2, off);
    }
    if ((t & 31) == 0) { red[t >> 5] = s; red[8 + (t >> 5)] = s2; }
    __syncthreads();
    float sum = 0.f, sum2 = 0.f;
    #pragma unroll
    for (int i = 0; i < 8; i++) { sum += red[i]; sum2 += red[8 + i]; }
    float mu = sum * (1.f / 256.f);
    float var = sum2 * (1.f / 256.f) - mu * mu;
    float r = rsqrtf(var + 1e-5f);
    float val = (x - mu) * r * gamma[t] + beta[t];
    float vn = __shfl_xor_sync(0xffffffffu, val, 1);
    if (!(t & 1)) {
        u32 hh = pk2(val, vn);
        u32 ll = pk2(val - lo_f(hh), vn - hi_f(hh));
        g_xh[(size_t)row * 128 + (t >> 1)] = hh;
        g_xl[(size_t)row * 128 + (t >> 1)] = ll;
    }
}

// ---------------- weight pre-split ----------------
__global__ void __launch_bounds__(256) wcvt_kernel(
    const float* __restrict__ Wqkv, const float* __restrict__ Wproj)
{
    int i = blockIdx.x * 256 + threadIdx.x;
    if (i < 256 * 384) {
        float a = Wqkv[2 * i], b = Wqkv[2 * i + 1];
        u32 hh = pk2(a, b);
        g_wqh[i] = hh;
        g_wql[i] = pk2(a - lo_f(hh), b - hi_f(hh));
    } else {
        int j = i - 256 * 384;
        if (j < 256 * 128) {
            float a = Wproj[2 * j], b = Wproj[2 * j + 1];
            u32 hh = pk2(a, b);
            g_wph[j] = hh;
            g_wpl[j] = pk2(a - lo_f(hh), b - hi_f(hh));
        }
    }
}

// ---------------- bias table ----------------
__global__ void __launch_bounds__(256) tab_kernel(
    const float* __restrict__ Wb1, const float* __restrict__ bb1,
    const float* __restrict__ Wb2, const float* __restrict__ bb2,
    const float* __restrict__ Wb3, const float* __restrict__ bb3)
{
    __shared__ float w1[64], c1[64], w2[4096], c2[64], w3[512], c3[8];
    int t = threadIdx.x;
    if (t < 64) { w1[t] = Wb1[t]; c1[t] = bb1[t]; c2[t] = bb2[t]; }
    if (t < 8)  c3[t] = bb3[t];
    for (int i = t; i < 4096; i += 256) w2[i] = Wb2[i];
    for (int i = t; i < 512;  i += 256) w3[i] = Wb3[i];
    __syncthreads();
    int idx = blockIdx.x * 256 + t;
    float d = -1.f + 2.f * (float)idx / (float)(kT - 1);
    float h1[64];
    #pragma unroll
    for (int u = 0; u < 64; u++) {
        float a = fmaf(d, w1[u], c1[u]);
        h1[u] = a / (1.f + expf(-a));
    }
    float acc[8];
    #pragma unroll
    for (int m = 0; m < 8; m++) acc[m] = c3[m];
    for (int u2 = 0; u2 < 64; u2++) {
        float a = c2[u2];
        #pragma unroll
        for (int u = 0; u < 64; u++) a = fmaf(h1[u], w2[u * 64 + u2], a);
        float sv = a / (1.f + expf(-a));
        #pragma unroll
        for (int m = 0; m < 8; m++) acc[m] = fmaf(sv, w3[u2 * 8 + m], acc[m]);
    }
    #pragma unroll
    for (int m = 0; m < 8; m++) g_tab[m * kT + idx] = acc[m] * 1.4426950408889634f;
}

// ---------------- HMMA GEMM, cp.async double-buffered, templated N tile ----------------
// CTA tile 128 x (NBLK*16), 8 warps. Single wave when grid <= 2*SMs.
template<int NBLK, bool PACKED_OUT>
__global__ void __launch_bounds__(256, 2) gemm_h(
    const u32* __restrict__ Ah, const u32* __restrict__ Al, int aStr,
    const u32* __restrict__ Wh, const u32* __restrict__ Wl, int wStr,
    const float* __restrict__ bias, const float* __restrict__ resid,
    float* __restrict__ C, u32* __restrict__ outH, u32* __restrict__ outL,
    int N, int K)
{
    constexpr int WS   = NBLK * 32 + 16;      // W smem row stride (bytes)
    constexpr int WBUF = 32 * WS;             // one W buffer (bytes)
    constexpr int GO_AH = 0, GO_AL = 20480;
    constexpr int GO_WH = 40960, GO_WL = 40960 + 2 * WBUF;

    extern __shared__ char smg[];
    const u32 smb = smem_u32(smg);

    const int n0 = blockIdx.x * (NBLK * 16), m0 = blockIdx.y * 128;
    const int t = threadIdx.x, w = t >> 5, lane = t & 31;
    const int r1 = lane >> 2;
    const int KC = K / 32;

    auto stage = [&](int c, int bb) {
        int k0 = c * 32;
        #pragma unroll
        for (int i = 0; i < 2; i++) {
            int idx = t + i * 256;
            int row = idx >> 2, q4 = idx & 3;
            size_t src = (size_t)(m0 + row) * aStr + (k0 >> 1) + q4 * 4;
            u32 doff = bb * 10240 + row * 80 + q4 * 16;
            cp16(smb + GO_AH + doff, Ah + src);
            cp16(smb + GO_AL + doff, Al + src);
        }
        #pragma unroll
        for (int i = 0; i < NBLK / 4; i++) {
            int idx = t + i * 256;
            int row = idx / (2 * NBLK), q4 = idx % (2 * NBLK);
            size_t src = (size_t)(k0 + row) * wStr + (n0 >> 1) + q4 * 4;
            u32 doff = bb * WBUF + row * WS + q4 * 16;
            cp16(smb + GO_WH + doff, Wh + src);
            cp16(smb + GO_WL + doff, Wl + src);
        }
    };

    float o[2 * NBLK][4] = {};

    stage(0, 0);
    CP_COMMIT();

    for (int c = 0; c < KC; c++) {
        int bb = c & 1;
        if (c + 1 < KC) { stage(c + 1, bb ^ 1); CP_COMMIT(); CP_WAIT(1); }
        else CP_WAIT(0);
        __syncthreads();

        u32 abase = smb + GO_AH + bb * 10240;
        u32 wbase = smb + GO_WH + bb * WBUF;
        #pragma unroll
        for (int ks = 0; ks < 2; ks++) {
            u32 aAh[4], aAl[4];
            u32 qa = abase + (16 * w + (lane & 15)) * 80 + ks * 32 + ((lane >> 4) << 4);
            ldsm_x4(aAh, qa);
            ldsm_x4(aAl, qa + (GO_AL - GO_AH));
            #pragma unroll
            for (int nb = 0; nb < NBLK; nb++) {
                u32 whf[4], wlf[4];
                u32 wa = wbase + (ks * 16 + (lane & 15)) * WS + nb * 32 + ((lane >> 4) << 4);
                ldsm_x4_t(whf, wa);
                ldsm_x4_t(wlf, wa + (GO_WL - GO_WH));
                mma_bf16(o[2 * nb],     aAh, whf[0], whf[1]);
                mma_bf16(o[2 * nb + 1], aAh, whf[2], whf[3]);
                mma_bf16(o[2 * nb],     aAl, whf[0], whf[1]);
                mma_bf16(o[2 * nb + 1], aAl, whf[2], whf[3]);
                mma_bf16(o[2 * nb],     aAh, wlf[0], wlf[1]);
                mma_bf16(o[2 * nb + 1], aAh, wlf[2], wlf[3]);
            }
        }
        __syncthreads();
    }

    const float QSCALE = 1.4426950408889634f / 5.656854249492381f;
    int row1 = m0 + 16 * w + r1;
    #pragma unroll
    for (int nb2 = 0; nb2 < 2 * NBLK; nb2++) {
        int col = n0 + nb2 * 8 + 2 * (lane & 3);
        float b0 = bias[col], b1 = bias[col + 1];
        float v00 = o[nb2][0] + b0, v01 = o[nb2][1] + b1;
        float v10 = o[nb2][2] + b0, v11 = o[nb2][3] + b1;
        if (PACKED_OUT) {
            float sc = (col < 256) ? QSCALE : 1.f;
            v00 *= sc; v01 *= sc; v10 *= sc; v11 *= sc;
            u32 h0 = pk2(v00, v01), h1 = pk2(v10, v11);
            u32 l0 = pk2(v00 - lo_f(h0), v01 - hi_f(h0));
            u32 l1 = pk2(v10 - lo_f(h1), v11 - hi_f(h1));
            size_t o0 = (size_t)row1 * (N >> 1) + (col >> 1);
            size_t o1 = (size_t)(row1 + 8) * (N >> 1) + (col >> 1);
            outH[o0] = h0; outL[o0] = l0;
            outH[o1] = h1; outL[o1] = l1;
        } else {
            v00 += resid[(size_t)row1 * N + col];
            v01 += resid[(size_t)row1 * N + col + 1];
            v10 += resid[(size_t)(row1 + 8) * N + col];
            v11 += resid[(size_t)(row1 + 8) * N + col + 1];
            *(float2*)(C + (size_t)row1 * N + col)       = make_float2(v00, v01);
            *(float2*)(C + (size_t)(row1 + 8) * N + col) = make_float2(v10, v11);
        }
    }
}

// ---------------- HMMA flash attention, cp.async double-buffered ----------------
__global__ void __launch_bounds__(256, 2) attn_kernel(
    const float* __restrict__ coord, const int* __restrict__ mask)
{
    extern __shared__ char smc[];
    float2* TB2 = (float2*)smc;
    const u32 smb = smem_u32(smc);

    const int qt = blockIdx.x, h = blockIdx.y, b = blockIdx.z;
    const int q0 = qt * 128;
    const int t = threadIdx.x, w = t >> 5, lane = t & 31;

    auto prefetch = [&](int tile, int bb) {
        int j0 = tile * 64;
        int row = t >> 2, q4 = t & 3;
        size_t base = (size_t)(b * kN + j0 + row) * 384 + h * 16 + q4 * 4;
        u32 doff = bb * 5120 + row * 80 + q4 * 16;
        cp16(smb + SO_KHI + doff, g_qkvh + base + 128);
        cp16(smb + SO_KLO + doff, g_qkvl + base + 128);
        cp16(smb + SO_VHI + doff, g_qkvh + base + 256);
        cp16(smb + SO_VLO + doff, g_qkvl + base + 256);
        if (t < 16)      cp16(smb + SO_CK + bb * 256 + t * 16, coord + b * kN + j0 + t * 4);
        else if (t < 32) cp16(smb + SO_MK + bb * 256 + (t - 16) * 16, mask + b * kN + j0 + (t - 16) * 4);
    };

    prefetch(0, 0);
    CP_COMMIT();

    #pragma unroll
    for (int i = 0; i < 8; i++) {
        int idx = t + i * 256;
        float f0 = g_tab[h * kT + idx];
        float f1 = g_tab[h * kT + (idx < kT - 1 ? idx + 1 : kT - 1)];
        TB2[idx] = make_float2(f0, f1);
    }
    #pragma unroll
    for (int i = 0; i < 2; i++) {
        int idx = t + i * 256;
        int row = idx >> 2, q4 = idx & 3;
        size_t src = (size_t)(b * kN + q0 + row) * 384 + h * 16 + q4 * 4;
        *(uint4*)(smc + SO_QHI + row * 80 + q4 * 16) = *(const uint4*)(g_qkvh + src);
        *(uint4*)(smc + SO_QLO + row * 80 + q4 * 16) = *(const uint4*)(g_qkvl + src);
    }
    __syncthreads();

    u32 aQh[2][4], aQl[2][4];
    {
        u32 qa = smb + SO_QHI + (16 * w + (lane & 15)) * 80 + ((lane >> 4) << 4);
        ldsm_x4(aQh[0], qa);
        ldsm_x4(aQh[1], qa + 32);
        ldsm_x4(aQl[0], qa + (SO_QLO - SO_QHI));
        ldsm_x4(aQl[1], qa + (SO_QLO - SO_QHI) + 32);
    }

    const int r1 = lane >> 2;
    const float cq1 = coord[b * kN + q0 + 16 * w + r1];
    const float cq2 = coord[b * kN + q0 + 16 * w + r1 + 8];
    const float aq1 = fmaf(-cq1, 1023.5f, 1023.5f);
    const float aq2 = fmaf(-cq2, 1023.5f, 1023.5f);

    float m1 = -1e30f, m2 = -1e30f, l1 = 0.f, l2 = 0.f;
    float o[4][4] = {};

    for (int tile = 0; tile < 16; tile++) {
        const int cur = tile & 1;
        if (tile + 1 < 16) { prefetch(tile + 1, cur ^ 1); CP_COMMIT(); CP_WAIT(1); }
        else CP_WAIT(0);
        __syncthreads();

        const float* ck = (const float*)(smc + SO_CK + cur * 256);
        const int*  mkp = (const int*)  (smc + SO_MK + cur * 256);
        const u32 kbase = smb + SO_KHI + cur * 5120;
        const u32 vbase = smb + SO_VHI + cur * 5120;

        float sacc[8][4];
        #pragma unroll
        for (int i = 0; i < 8; i++)
            { sacc[i][0] = 0.f; sacc[i][1] = 0.f; sacc[i][2] = 0.f; sacc[i][3] = 0.f; }
        #pragma unroll
        for (int ks = 0; ks < 2; ks++) {
            #pragma unroll
            for (int nb = 0; nb < 4; nb++) {
                u32 kh[4], kl[4];
                u32 ka = kbase + (nb * 16 + (lane & 15)) * 80 + ks * 32 + ((lane >> 4) << 4);
                ldsm_x4(kh, ka);
                ldsm_x4(kl, ka + (SO_KLO - SO_KHI));
                mma_bf16(sacc[2 * nb],     aQh[ks], kh[0], kh[2]);
                mma_bf16(sacc[2 * nb + 1], aQh[ks], kh[1], kh[3]);
                mma_bf16(sacc[2 * nb],     aQl[ks], kh[0], kh[2]);
                mma_bf16(sacc[2 * nb + 1], aQl[ks], kh[1], kh[3]);
                mma_bf16(sacc[2 * nb],     aQh[ks], kl[0], kl[2]);
                mma_bf16(sacc[2 * nb + 1], aQh[ks], kl[1], kl[3]);
            }
        }

        float mx1 = m1, mx2 = m2;
        #pragma unroll
        for (int cb = 0; cb < 8; cb++) {
            int c0 = cb * 8 + 2 * (lane & 3);
            float ck0 = ck[c0], ck1 = ck[c0 + 1];
            int mk0 = mkp[c0], mk1 = mkp[c0 + 1];
            float u00 = fmaf(ck0, 1023.5f, aq1), u01 = fmaf(ck1, 1023.5f, aq1);
            float u10 = fmaf(ck0, 1023.5f, aq2), u11 = fmaf(ck1, 1023.5f, aq2);
            int i00 = (int)u00, i01 = (int)u01, i10 = (int)u10, i11 = (int)u11;
            float2 t00 = TB2[i00], t01 = TB2[i01], t10 = TB2[i10], t11 = TB2[i11];
            float s00 = sacc[cb][0] + fmaf(u00 - (float)i00, t00.y - t00.x, t00.x);
            float s01 = sacc[cb][1] + fmaf(u01 - (float)i01, t01.y - t01.x, t01.x);
            float s10 = sacc[cb][2] + fmaf(u10 - (float)i10, t10.y - t10.x, t10.x);
            float s11 = sacc[cb][3] + fmaf(u11 - (float)i11, t11.y - t11.x, t11.x);
            if (!mk0) { s00 = -1e38f; s10 = -1e38f; }
            if (!mk1) { s01 = -1e38f; s11 = -1e38f; }
            sacc[cb][0] = s00; sacc[cb][1] = s01; sacc[cb][2] = s10; sacc[cb][3] = s11;
            mx1 = fmaxf(mx1, fmaxf(s00, s01));
            mx2 = fmaxf(mx2, fmaxf(s10, s11));
        }
        mx1 = fmaxf(mx1, __shfl_xor_sync(0xffffffffu, mx1, 1));
        mx1 = fmaxf(mx1, __shfl_xor_sync(0xffffffffu, mx1, 2));
        mx2 = fmaxf(mx2, __shfl_xor_sync(0xffffffffu, mx2, 1));
        mx2 = fmaxf(mx2, __shfl_xor_sync(0xffffffffu, mx2, 2));
        float co1 = ex2(m1 - mx1), co2 = ex2(m2 - mx2);
        m1 = mx1; m2 = mx2;
        #pragma unroll
        for (int db = 0; db < 4; db++) {
            o[db][0] *= co1; o[db][1] *= co1; o[db][2] *= co2; o[db][3] *= co2;
        }

        float su1 = 0.f, su2 = 0.f;
        u32 phi[16];
        #pragma unroll
        for (int cb = 0; cb < 8; cb++) {
            float p00 = ex2(sacc[cb][0] - m1), p01 = ex2(sacc[cb][1] - m1);
            float p10 = ex2(sacc[cb][2] - m2), p11 = ex2(sacc[cb][3] - m2);
            su1 += p00 + p01; su2 += p10 + p11;
            phi[2 * cb]     = pk2(p00, p01);
            phi[2 * cb + 1] = pk2(p10, p11);
        }
        l1 = l1 * co1 + su1;   // quad-partial; co quad-uniform; reduced at end
        l2 = l2 * co2 + su2;

        #pragma unroll
        for (int kc = 0; kc < 4; kc++) {
            #pragma unroll
            for (int dp = 0; dp < 2; dp++) {
                u32 vh[4], vl[4];
                u32 va = vbase + (16 * kc + (lane & 15)) * 80 + dp * 32 + ((lane >> 4) << 4);
                ldsm_x4_t(vh, va);
                ldsm_x4_t(vl, va + (SO_VLO - SO_VHI));
                mma_bf16(o[2 * dp],     &phi[4 * kc], vh[0], vh[1]);
                mma_bf16(o[2 * dp + 1], &phi[4 * kc], vh[2], vh[3]);
                mma_bf16(o[2 * dp],     &phi[4 * kc], vl[0], vl[1]);
                mma_bf16(o[2 * dp + 1], &phi[4 * kc], vl[2], vl[3]);
            }
        }
        __syncthreads();
    }

    l1 += __shfl_xor_sync(0xffffffffu, l1, 1);
    l1 += __shfl_xor_sync(0xffffffffu, l1, 2);
    l2 += __shfl_xor_sync(0xffffffffu, l2, 1);
    l2 += __shfl_xor_sync(0xffffffffu, l2, 2);

    float inv1 = 1.f / l1, inv2 = 1.f / l2;
    int row1 = b * kN + q0 + 16 * w + r1;
    #pragma unroll
    for (int db = 0; db < 4; db++) {
        int c = h * 32 + db * 8 + 2 * (lane & 3);
        float v00 = o[db][0] * inv1, v01 = o[db][1] * inv1;
        float v10 = o[db][2] * inv2, v11 = o[db][3] * inv2;
        u32 h0 = pk2(v00, v01), h1 = pk2(v10, v11);
        u32 l0 = pk2(v00 - lo_f(h0), v01 - hi_f(h0));
        u32 l1p = pk2(v10 - lo_f(h1), v11 - hi_f(h1));
        g_aoh[(size_t)row1 * 128 + (c >> 1)] = h0;
        g_aol[(size_t)row1 * 128 + (c >> 1)] = l0;
        g_aoh[(size_t)(row1 + 8) * 128 + (c >> 1)] = h1;
        g_aol[(size_t)(row1 + 8) * 128 + (c >> 1)] = l1p;
    }
}

// ---------------- launch ----------------
extern "C" void kernel_launch(void* const* d_in, const int* in_sizes, int n_in,
                              void* d_out, int out_size)
{
    const float* hin   = (const float*)d_in[0];
    const float* coord = (const float*)d_in[1];
    const int*   mask  = (const int*)  d_in[2];
    const float* Wqkv  = (const float*)d_in[3];
    const float* bqkv  = (const float*)d_in[4];
    const float* Wproj = (const float*)d_in[5];
    const float* bproj = (const float*)d_in[6];
    const float* gamma = (const float*)d_in[7];
    const float* beta  = (const float*)d_in[8];
    const float* Wb1 = (const float*)d_in[9],  *bb1 = (const float*)d_in[10];
    const float* Wb2 = (const float*)d_in[11], *bb2 = (const float*)d_in[12];
    const float* Wb3 = (const float*)d_in[13], *bb3 = (const float*)d_in[14];
    float* out = (float*)d_out;

    void *p_xh, *p_xl, *p_qh, *p_ql, *p_wqh, *p_wql, *p_wph, *p_wpl, *p_aoh, *p_aol;
    cudaGetSymbolAddress(&p_xh, g_xh);   cudaGetSymbolAddress(&p_xl, g_xl);
    cudaGetSymbolAddress(&p_qh, g_qkvh); cudaGetSymbolAddress(&p_ql, g_qkvl);
    cudaGetSymbolAddress(&p_wqh, g_wqh); cudaGetSymbolAddress(&p_wql, g_wql);
    cudaGetSymbolAddress(&p_wph, g_wph); cudaGetSymbolAddress(&p_wpl, g_wpl);
    cudaGetSymbolAddress(&p_aoh, g_aoh); cudaGetSymbolAddress(&p_aol, g_aol);

    // smem sizes: NBLK=8 -> 40960 + 4*32*272 = 75776 ; NBLK=4 -> 59392
    constexpr int GEMM8_SMEM = 40960 + 4 * 32 * (8 * 32 + 16);
    constexpr int GEMM4_SMEM = 40960 + 4 * 32 * (4 * 32 + 16);

    cudaFuncSetAttribute(attn_kernel, cudaFuncAttributeMaxDynamicSharedMemorySize, ATTN_SMEM);
    cudaFuncSetAttribute(gemm_h<8, true>,  cudaFuncAttributeMaxDynamicSharedMemorySize, GEMM8_SMEM);
    cudaFuncSetAttribute(gemm_h<4, false>, cudaFuncAttributeMaxDynamicSharedMemorySize, GEMM4_SMEM);

    tab_kernel<<<kT / 256, 256>>>(Wb1, bb1, Wb2, bb2, Wb3, bb3);
    wcvt_kernel<<<512, 256>>>(Wqkv, Wproj);
    ln_kernel<<<kROWS, 256>>>(hin, gamma, beta);
    // qkv (packed out, Q pre-scaled): 128x128 CTA tile -> grid 6x32 = 192 CTAs (one wave)
    gemm_h<8, true><<<dim3(768 / 128, kROWS / 128), 256, GEMM8_SMEM>>>(
        (const u32*)p_xh, (const u32*)p_xl, 128,
        (const u32*)p_wqh, (const u32*)p_wql, 384,
        bqkv, nullptr, nullptr, (u32*)p_qh, (u32*)p_ql, 768, 256);
    attn_kernel<<<dim3(kN / 128, kNH, kB), 256, ATTN_SMEM>>>(coord, mask);
    // out = h + ao @ Wproj + bproj: 128x64 tile -> grid 4x32 = 128 CTAs
    gemm_h<4, false><<<dim3(256 / 64, kROWS / 128), 256, GEMM4_SMEM>>>(
        (const u32*)p_aoh, (const u32*)p_aol, 128,
        (const u32*)p_wph, (const u32*)p_wpl, 128,
        bproj, hin, out, nullptr, nullptr, 256, 256);
}

// round 16
// speedup vs baseline: 1.0350x; 1.0350x over previous
#include <cuda_runtime.h>
#include <cuda_bf16.h>
#include <math.h>
#include <stdint.h>

typedef unsigned long long u64;
typedef uint32_t u32;

constexpr int kB = 4, kN = 1024, kNH = 8, kHID = 256;
constexpr int kROWS = kB * kN;
constexpr int kT = 2048;

// ---- attn smem layout (bytes), K/V/ck/mk double-buffered ----
constexpr int SO_CK  = 16384;              // 2 x 256
constexpr int SO_MK  = 16896;              // 2 x 256
constexpr int SO_QHI = 17408, SO_QLO = 27648;              // 10240 each
constexpr int SO_KHI = 37888, SO_KLO = 48128;              // 2 x 5120 each
constexpr int SO_VHI = 58368, SO_VLO = 68608;
constexpr int ATTN_SMEM = 78848;

// ---- gemm smem layout (bytes), double-buffered ----
constexpr int GO_AH = 0, GO_AL = 20480;    // 2 x 10240 each
constexpr int GO_WH = 40960, GO_WL = 50176; // 2 x 4608 each
constexpr int GEMM_SMEM = 59392;

// ---- packed bf16 hi/lo scratch (u32 = 2 bf16) ----
__device__ u32 g_xh  [kROWS * 128], g_xl  [kROWS * 128];   // LN output
__device__ u32 g_qkvh[kROWS * 384], g_qkvl[kROWS * 384];   // qkv (q pre-scaled)
__device__ u32 g_wqh [256 * 384],   g_wql [256 * 384];     // Wqkv
__device__ u32 g_wph [256 * 128],   g_wpl [256 * 128];     // Wproj
__device__ u32 g_aoh [kROWS * 128], g_aol [kROWS * 128];   // attention output
__device__ float g_tab[kNH * kT];                          // head-major, log2e pre-scaled

// ---------------- helpers ----------------
__device__ __forceinline__ u32 smem_u32(const void* p) {
    u32 a;
    asm("{ .reg .u64 t; cvta.to.shared.u64 t, %1; cvt.u32.u64 %0, t; }" : "=r"(a) : "l"(p));
    return a;
}
__device__ __forceinline__ void cp16(u32 dst, const void* src) {
    asm volatile("cp.async.cg.shared.global [%0], [%1], 16;" :: "r"(dst), "l"(src));
}
#define CP_COMMIT() asm volatile("cp.async.commit_group;" ::: "memory")
#define CP_WAIT(n)  asm volatile("cp.async.wait_group %0;" :: "n"(n) : "memory")
__device__ __forceinline__ void ldsm_x4(u32* r, u32 a) {
    asm volatile("ldmatrix.sync.aligned.m8n8.x4.shared.b16 {%0,%1,%2,%3}, [%4];"
        : "=r"(r[0]), "=r"(r[1]), "=r"(r[2]), "=r"(r[3]) : "r"(a));
}
__device__ __forceinline__ void ldsm_x4_t(u32* r, u32 a) {
    asm volatile("ldmatrix.sync.aligned.m8n8.x4.trans.shared.b16 {%0,%1,%2,%3}, [%4];"
        : "=r"(r[0]), "=r"(r[1]), "=r"(r[2]), "=r"(r[3]) : "r"(a));
}
__device__ __forceinline__ void mma_bf16(float* d, const u32* a, u32 b0, u32 b1) {
    asm volatile(
        "mma.sync.aligned.m16n8k16.row.col.f32.bf16.bf16.f32 "
        "{%0,%1,%2,%3}, {%4,%5,%6,%7}, {%8,%9}, {%0,%1,%2,%3};"
        : "+f"(d[0]), "+f"(d[1]), "+f"(d[2]), "+f"(d[3])
        : "r"(a[0]), "r"(a[1]), "r"(a[2]), "r"(a[3]), "r"(b0), "r"(b1));
}
__device__ __forceinline__ float ex2(float x) {
    float y; asm("ex2.approx.f32 %0, %1;" : "=f"(y) : "f"(x)); return y;
}
__device__ __forceinline__ u32 pk2(float a, float b) {
    __nv_bfloat162 t = __floats2bfloat162_rn(a, b);
    return *reinterpret_cast<u32*>(&t);
}
__device__ __forceinline__ float lo_f(u32 h) { return __uint_as_float(h << 16); }
__device__ __forceinline__ float hi_f(u32 h) { return __uint_as_float(h & 0xffff0000u); }

// ---------------- LayerNorm -> packed hi/lo ----------------
__global__ void ln_kernel(const float* __restrict__ hin, const float* __restrict__ gamma,
                          const float* __restrict__ beta)
{
    __shared__ float red[16];
    int row = blockIdx.x, t = threadIdx.x;
    float x = hin[(size_t)row * kHID + t];
    float s = x, s2 = x * x;
    #pragma unroll
    for (int off = 16; off; off >>= 1) {
        s  += __shfl_xor_sync(0xffffffffu, s,  off);
        s2 += __shfl_xor_sync(0xffffffffu, s2, off);
    }
    if ((t & 31) == 0) { red[t >> 5] = s; red[8 + (t >> 5)] = s2; }
    __syncthreads();
    float sum = 0.f, sum2 = 0.f;
    #pragma unroll
    for (int i = 0; i < 8; i++) { sum += red[i]; sum2 += red[8 + i]; }
    float mu = sum * (1.f / 256.f);
    float var = sum2 * (1.f / 256.f) - mu * mu;
    float r = rsqrtf(var + 1e-5f);
    float val = (x - mu) * r * gamma[t] + beta[t];
    float vn = __shfl_xor_sync(0xffffffffu, val, 1);
    if (!(t & 1)) {
        u32 hh = pk2(val, vn);
        u32 ll = pk2(val - lo_f(hh), vn - hi_f(hh));
        g_xh[(size_t)row * 128 + (t >> 1)] = hh;
        g_xl[(size_t)row * 128 + (t >> 1)] = ll;
    }
}

// ---------------- weight pre-split ----------------
__global__ void __launch_bounds__(256) wcvt_kernel(
    const float* __restrict__ Wqkv, const float* __restrict__ Wproj)
{
    int i = blockIdx.x * 256 + threadIdx.x;
    if (i < 256 * 384) {
        float a = Wqkv[2 * i], b = Wqkv[2 * i + 1];
        u32 hh = pk2(a, b);
        g_wqh[i] = hh;
        g_wql[i] = pk2(a - lo_f(hh), b - hi_f(hh));
    } else {
        int j = i - 256 * 384;
        if (j < 256 * 128) {
            float a = Wproj[2 * j], b = Wproj[2 * j + 1];
            u32 hh = pk2(a, b);
            g_wph[j] = hh;
            g_wpl[j] = pk2(a - lo_f(hh), b - hi_f(hh));
        }
    }
}

// ---------------- bias table ----------------
__global__ void __launch_bounds__(256) tab_kernel(
    const float* __restrict__ Wb1, const float* __restrict__ bb1,
    const float* __restrict__ Wb2, const float* __restrict__ bb2,
    const float* __restrict__ Wb3, const float* __restrict__ bb3)
{
    __shared__ float w1[64], c1[64], w2[4096], c2[64], w3[512], c3[8];
    int t = threadIdx.x;
    if (t < 64) { w1[t] = Wb1[t]; c1[t] = bb1[t]; c2[t] = bb2[t]; }
    if (t < 8)  c3[t] = bb3[t];
    for (int i = t; i < 4096; i += 256) w2[i] = Wb2[i];
    for (int i = t; i < 512;  i += 256) w3[i] = Wb3[i];
    __syncthreads();
    int idx = blockIdx.x * 256 + t;
    float d = -1.f + 2.f * (float)idx / (float)(kT - 1);
    float h1[64];
    #pragma unroll
    for (int u = 0; u < 64; u++) {
        float a = fmaf(d, w1[u], c1[u]);
        h1[u] = a / (1.f + expf(-a));
    }
    float acc[8];
    #pragma unroll
    for (int m = 0; m < 8; m++) acc[m] = c3[m];
    for (int u2 = 0; u2 < 64; u2++) {
        float a = c2[u2];
        #pragma unroll
        for (int u = 0; u < 64; u++) a = fmaf(h1[u], w2[u * 64 + u2], a);
        float sv = a / (1.f + expf(-a));
        #pragma unroll
        for (int m = 0; m < 8; m++) acc[m] = fmaf(sv, w3[u2 * 8 + m], acc[m]);
    }
    #pragma unroll
    for (int m = 0; m < 8; m++) g_tab[m * kT + idx] = acc[m] * 1.4426950408889634f;
}

// ---------------- HMMA GEMM, cp.async double-buffered, 3 CTAs/SM ----------------
// CTA tile 128 x 64, 8 warps. PACKED_OUT: emit hi/lo u32 (QSCALE on cols<256).
template<bool PACKED_OUT>
__global__ void __launch_bounds__(256, 3) gemm_h(
    const u32* __restrict__ Ah, const u32* __restrict__ Al, int aStr,
    const u32* __restrict__ Wh, const u32* __restrict__ Wl, int wStr,
    const float* __restrict__ bias, const float* __restrict__ resid,
    float* __restrict__ C, u32* __restrict__ outH, u32* __restrict__ outL,
    int N, int K)
{
    extern __shared__ char smg[];
    const u32 smb = smem_u32(smg);

    const int n0 = blockIdx.x * 64, m0 = blockIdx.y * 128;
    const int t = threadIdx.x, w = t >> 5, lane = t & 31;
    const int r1 = lane >> 2;
    const int KC = K / 32;

    auto stage = [&](int c, int bb) {
        int k0 = c * 32;
        #pragma unroll
        for (int i = 0; i < 2; i++) {
            int idx = t + i * 256;
            int row = idx >> 2, q4 = idx & 3;
            size_t src = (size_t)(m0 + row) * aStr + (k0 >> 1) + q4 * 4;
            u32 doff = bb * 10240 + row * 80 + q4 * 16;
            cp16(smb + GO_AH + doff, Ah + src);
            cp16(smb + GO_AL + doff, Al + src);
        }
        {
            int row = t >> 3, q4 = t & 7;
            size_t src = (size_t)(k0 + row) * wStr + (n0 >> 1) + q4 * 4;
            u32 doff = bb * 4608 + row * 144 + q4 * 16;
            cp16(smb + GO_WH + doff, Wh + src);
            cp16(smb + GO_WL + doff, Wl + src);
        }
    };

    float o[8][4] = {};

    stage(0, 0);
    CP_COMMIT();

    for (int c = 0; c < KC; c++) {
        int bb = c & 1;
        if (c + 1 < KC) { stage(c + 1, bb ^ 1); CP_COMMIT(); CP_WAIT(1); }
        else CP_WAIT(0);
        __syncthreads();

        u32 abase = smb + GO_AH + bb * 10240;
        u32 wbase = smb + GO_WH + bb * 4608;
        #pragma unroll
        for (int ks = 0; ks < 2; ks++) {
            u32 aAh[4], aAl[4];
            u32 qa = abase + (16 * w + (lane & 15)) * 80 + ks * 32 + ((lane >> 4) << 4);
            ldsm_x4(aAh, qa);
            ldsm_x4(aAl, qa + (GO_AL - GO_AH));
            #pragma unroll
            for (int nb = 0; nb < 4; nb++) {
                u32 whf[4], wlf[4];
                u32 wa = wbase + (ks * 16 + (lane & 15)) * 144 + nb * 32 + ((lane >> 4) << 4);
                ldsm_x4_t(whf, wa);
                ldsm_x4_t(wlf, wa + (GO_WL - GO_WH));
                mma_bf16(o[2 * nb],     aAh, whf[0], whf[1]);
                mma_bf16(o[2 * nb + 1], aAh, whf[2], whf[3]);
                mma_bf16(o[2 * nb],     aAl, whf[0], whf[1]);
                mma_bf16(o[2 * nb + 1], aAl, whf[2], whf[3]);
                mma_bf16(o[2 * nb],     aAh, wlf[0], wlf[1]);
                mma_bf16(o[2 * nb + 1], aAh, wlf[2], wlf[3]);
            }
        }
        __syncthreads();
    }

    const float QSCALE = 1.4426950408889634f / 5.656854249492381f;
    int row1 = m0 + 16 * w + r1;
    #pragma unroll
    for (int nb2 = 0; nb2 < 8; nb2++) {
        int col = n0 + nb2 * 8 + 2 * (lane & 3);
        float b0 = bias[col], b1 = bias[col + 1];
        float v00 = o[nb2][0] + b0, v01 = o[nb2][1] + b1;
        float v10 = o[nb2][2] + b0, v11 = o[nb2][3] + b1;
        if (PACKED_OUT) {
            float sc = (col < 256) ? QSCALE : 1.f;
            v00 *= sc; v01 *= sc; v10 *= sc; v11 *= sc;
            u32 h0 = pk2(v00, v01), h1 = pk2(v10, v11);
            u32 l0 = pk2(v00 - lo_f(h0), v01 - hi_f(h0));
            u32 l1 = pk2(v10 - lo_f(h1), v11 - hi_f(h1));
            size_t o0 = (size_t)row1 * (N >> 1) + (col >> 1);
            size_t o1 = (size_t)(row1 + 8) * (N >> 1) + (col >> 1);
            outH[o0] = h0; outL[o0] = l0;
            outH[o1] = h1; outL[o1] = l1;
        } else {
            v00 += resid[(size_t)row1 * N + col];
            v01 += resid[(size_t)row1 * N + col + 1];
            v10 += resid[(size_t)(row1 + 8) * N + col];
            v11 += resid[(size_t)(row1 + 8) * N + col + 1];
            *(float2*)(C + (size_t)row1 * N + col)       = make_float2(v00, v01);
            *(float2*)(C + (size_t)(row1 + 8) * N + col) = make_float2(v10, v11);
        }
    }
}

// ---------------- HMMA flash attention, cp.async double-buffered ----------------
__global__ void __launch_bounds__(256, 2) attn_kernel(
    const float* __restrict__ coord, const int* __restrict__ mask)
{
    extern __shared__ char smc[];
    float2* TB2 = (float2*)smc;
    const u32 smb = smem_u32(smc);

    const int qt = blockIdx.x, h = blockIdx.y, b = blockIdx.z;
    const int q0 = qt * 128;
    const int t = threadIdx.x, w = t >> 5, lane = t & 31;

    auto prefetch = [&](int tile, int bb) {
        int j0 = tile * 64;
        int row = t >> 2, q4 = t & 3;
        size_t base = (size_t)(b * kN + j0 + row) * 384 + h * 16 + q4 * 4;
        u32 doff = bb * 5120 + row * 80 + q4 * 16;
        cp16(smb + SO_KHI + doff, g_qkvh + base + 128);
        cp16(smb + SO_KLO + doff, g_qkvl + base + 128);
        cp16(smb + SO_VHI + doff, g_qkvh + base + 256);
        cp16(smb + SO_VLO + doff, g_qkvl + base + 256);
        if (t < 16)      cp16(smb + SO_CK + bb * 256 + t * 16, coord + b * kN + j0 + t * 4);
        else if (t < 32) cp16(smb + SO_MK + bb * 256 + (t - 16) * 16, mask + b * kN + j0 + (t - 16) * 4);
    };

    prefetch(0, 0);
    CP_COMMIT();

    #pragma unroll
    for (int i = 0; i < 8; i++) {
        int idx = t + i * 256;
        float f0 = g_tab[h * kT + idx];
        float f1 = g_tab[h * kT + (idx < kT - 1 ? idx + 1 : kT - 1)];
        TB2[idx] = make_float2(f0, f1);
    }
    #pragma unroll
    for (int i = 0; i < 2; i++) {
        int idx = t + i * 256;
        int row = idx >> 2, q4 = idx & 3;
        size_t src = (size_t)(b * kN + q0 + row) * 384 + h * 16 + q4 * 4;
        *(uint4*)(smc + SO_QHI + row * 80 + q4 * 16) = *(const uint4*)(g_qkvh + src);
        *(uint4*)(smc + SO_QLO + row * 80 + q4 * 16) = *(const uint4*)(g_qkvl + src);
    }
    __syncthreads();

    u32 aQh[2][4], aQl[2][4];
    {
        u32 qa = smb + SO_QHI + (16 * w + (lane & 15)) * 80 + ((lane >> 4) << 4);
        ldsm_x4(aQh[0], qa);
        ldsm_x4(aQh[1], qa + 32);
        ldsm_x4(aQl[0], qa + (SO_QLO - SO_QHI));
        ldsm_x4(aQl[1], qa + (SO_QLO - SO_QHI) + 32);
    }

    const int r1 = lane >> 2;
    const float cq1 = coord[b * kN + q0 + 16 * w + r1];
    const float cq2 = coord[b * kN + q0 + 16 * w + r1 + 8];
    const float aq1 = fmaf(-cq1, 1023.5f, 1023.5f);
    const float aq2 = fmaf(-cq2, 1023.5f, 1023.5f);

    float m1 = -1e30f, m2 = -1e30f, l1 = 0.f, l2 = 0.f;
    float o[4][4] = {};

    for (int tile = 0; tile < 16; tile++) {
        const int cur = tile & 1;
        if (tile + 1 < 16) { prefetch(tile + 1, cur ^ 1); CP_COMMIT(); CP_WAIT(1); }
        else CP_WAIT(0);
        __syncthreads();

        const float* ck = (const float*)(smc + SO_CK + cur * 256);
        const int*  mkp = (const int*)  (smc + SO_MK + cur * 256);
        const u32 kbase = smb + SO_KHI + cur * 5120;
        const u32 vbase = smb + SO_VHI + cur * 5120;

        float sacc[8][4];
        #pragma unroll
        for (int i = 0; i < 8; i++)
            { sacc[i][0] = 0.f; sacc[i][1] = 0.f; sacc[i][2] = 0.f; sacc[i][3] = 0.f; }
        #pragma unroll
        for (int ks = 0; ks < 2; ks++) {
            #pragma unroll
            for (int nb = 0; nb < 4; nb++) {
                u32 kh[4], kl[4];
                u32 ka = kbase + (nb * 16 + (lane & 15)) * 80 + ks * 32 + ((lane >> 4) << 4);
                ldsm_x4(kh, ka);
                ldsm_x4(kl, ka + (SO_KLO - SO_KHI));
                mma_bf16(sacc[2 * nb],     aQh[ks], kh[0], kh[2]);
                mma_bf16(sacc[2 * nb + 1], aQh[ks], kh[1], kh[3]);
                mma_bf16(sacc[2 * nb],     aQl[ks], kh[0], kh[2]);
                mma_bf16(sacc[2 * nb + 1], aQl[ks], kh[1], kh[3]);
                mma_bf16(sacc[2 * nb],     aQh[ks], kl[0], kl[2]);
                mma_bf16(sacc[2 * nb + 1], aQh[ks], kl[1], kl[3]);
            }
        }

        float mx1 = m1, mx2 = m2;
        #pragma unroll
        for (int cb = 0; cb < 8; cb++) {
            int c0 = cb * 8 + 2 * (lane & 3);
            float ck0 = ck[c0], ck1 = ck[c0 + 1];
            int mk0 = mkp[c0], mk1 = mkp[c0 + 1];
            float u00 = fmaf(ck0, 1023.5f, aq1), u01 = fmaf(ck1, 1023.5f, aq1);
            float u10 = fmaf(ck0, 1023.5f, aq2), u11 = fmaf(ck1, 1023.5f, aq2);
            int i00 = (int)u00, i01 = (int)u01, i10 = (int)u10, i11 = (int)u11;
            float2 t00 = TB2[i00], t01 = TB2[i01], t10 = TB2[i10], t11 = TB2[i11];
            float s00 = sacc[cb][0] + fmaf(u00 - (float)i00, t00.y - t00.x, t00.x);
            float s01 = sacc[cb][1] + fmaf(u01 - (float)i01, t01.y - t01.x, t01.x);
            float s10 = sacc[cb][2] + fmaf(u10 - (float)i10, t10.y - t10.x, t10.x);
            float s11 = sacc[cb][3] + fmaf(u11 - (float)i11, t11.y - t11.x, t11.x);
            if (!mk0) { s00 = -1e38f; s10 = -1e38f; }
            if (!mk1) { s01 = -1e38f; s11 = -1e38f; }
            sacc[cb][0] = s00; sacc[cb][1] = s01; sacc[cb][2] = s10; sacc[cb][3] = s11;
            mx1 = fmaxf(mx1, fmaxf(s00, s01));
            mx2 = fmaxf(mx2, fmaxf(s10, s11));
        }
        mx1 = fmaxf(mx1, __shfl_xor_sync(0xffffffffu, mx1, 1));
        mx1 = fmaxf(mx1, __shfl_xor_sync(0xffffffffu, mx1, 2));
        mx2 = fmaxf(mx2, __shfl_xor_sync(0xffffffffu, mx2, 1));
        mx2 = fmaxf(mx2, __shfl_xor_sync(0xffffffffu, mx2, 2));
        float co1 = ex2(m1 - mx1), co2 = ex2(m2 - mx2);
        m1 = mx1; m2 = mx2;
        #pragma unroll
        for (int db = 0; db < 4; db++) {
            o[db][0] *= co1; o[db][1] *= co1; o[db][2] *= co2; o[db][3] *= co2;
        }

        float su1 = 0.f, su2 = 0.f;
        u32 phi[16];
        #pragma unroll
        for (int cb = 0; cb < 8; cb++) {
            float p00 = ex2(sacc[cb][0] - m1), p01 = ex2(sacc[cb][1] - m1);
            float p10 = ex2(sacc[cb][2] - m2), p11 = ex2(sacc[cb][3] - m2);
            su1 += p00 + p01; su2 += p10 + p11;
            phi[2 * cb]     = pk2(p00, p01);
            phi[2 * cb + 1] = pk2(p10, p11);
        }
        l1 = l1 * co1 + su1;   // quad-partial; co quad-uniform; reduced at end
        l2 = l2 * co2 + su2;

        #pragma unroll
        for (int kc = 0; kc < 4; kc++) {
            #pragma unroll
            for (int dp = 0; dp < 2; dp++) {
                u32 vh[4], vl[4];
                u32 va = vbase + (16 * kc + (lane & 15)) * 80 + dp * 32 + ((lane >> 4) << 4);
                ldsm_x4_t(vh, va);
                ldsm_x4_t(vl, va + (SO_VLO - SO_VHI));
                mma_bf16(o[2 * dp],     &phi[4 * kc], vh[0], vh[1]);
                mma_bf16(o[2 * dp + 1], &phi[4 * kc], vh[2], vh[3]);
                mma_bf16(o[2 * dp],     &phi[4 * kc], vl[0], vl[1]);
                mma_bf16(o[2 * dp + 1], &phi[4 * kc], vl[2], vl[3]);
            }
        }
        __syncthreads();
    }

    l1 += __shfl_xor_sync(0xffffffffu, l1, 1);
    l1 += __shfl_xor_sync(0xffffffffu, l1, 2);
    l2 += __shfl_xor_sync(0xffffffffu, l2, 1);
    l2 += __shfl_xor_sync(0xffffffffu, l2, 2);

    float inv1 = 1.f / l1, inv2 = 1.f / l2;
    int row1 = b * kN + q0 + 16 * w + r1;
    #pragma unroll
    for (int db = 0; db < 4; db++) {
        int c = h * 32 + db * 8 + 2 * (lane & 3);
        float v00 = o[db][0] * inv1, v01 = o[db][1] * inv1;
        float v10 = o[db][2] * inv2, v11 = o[db][3] * inv2;
        u32 h0 = pk2(v00, v01), h1 = pk2(v10, v11);
        u32 l0 = pk2(v00 - lo_f(h0), v01 - hi_f(h0));
        u32 l1p = pk2(v10 - lo_f(h1), v11 - hi_f(h1));
        g_aoh[(size_t)row1 * 128 + (c >> 1)] = h0;
        g_aol[(size_t)row1 * 128 + (c >> 1)] = l0;
        g_aoh[(size_t)(row1 + 8) * 128 + (c >> 1)] = h1;
        g_aol[(size_t)(row1 + 8) * 128 + (c >> 1)] = l1p;
    }
}

// ---------------- launch ----------------
extern "C" void kernel_launch(void* const* d_in, const int* in_sizes, int n_in,
                              void* d_out, int out_size)
{
    const float* hin   = (const float*)d_in[0];
    const float* coord = (const float*)d_in[1];
    const int*   mask  = (const int*)  d_in[2];
    const float* Wqkv  = (const float*)d_in[3];
    const float* bqkv  = (const float*)d_in[4];
    const float* Wproj = (const float*)d_in[5];
    const float* bproj = (const float*)d_in[6];
    const float* gamma = (const float*)d_in[7];
    const float* beta  = (const float*)d_in[8];
    const float* Wb1 = (const float*)d_in[9],  *bb1 = (const float*)d_in[10];
    const float* Wb2 = (const float*)d_in[11], *bb2 = (const float*)d_in[12];
    const float* Wb3 = (const float*)d_in[13], *bb3 = (const float*)d_in[14];
    float* out = (float*)d_out;

    void *p_xh, *p_xl, *p_qh, *p_ql, *p_wqh, *p_wql, *p_wph, *p_wpl, *p_aoh, *p_aol;
    cudaGetSymbolAddress(&p_xh, g_xh);   cudaGetSymbolAddress(&p_xl, g_xl);
    cudaGetSymbolAddress(&p_qh, g_qkvh); cudaGetSymbolAddress(&p_ql, g_qkvl);
    cudaGetSymbolAddress(&p_wqh, g_wqh); cudaGetSymbolAddress(&p_wql, g_wql);
    cudaGetSymbolAddress(&p_wph, g_wph); cudaGetSymbolAddress(&p_wpl, g_wpl);
    cudaGetSymbolAddress(&p_aoh, g_aoh); cudaGetSymbolAddress(&p_aol, g_aol);

    cudaFuncSetAttribute(attn_kernel, cudaFuncAttributeMaxDynamicSharedMemorySize, ATTN_SMEM);
    cudaFuncSetAttribute(gemm_h<true>,  cudaFuncAttributeMaxDynamicSharedMemorySize, GEMM_SMEM);
    cudaFuncSetAttribute(gemm_h<false>, cudaFuncAttributeMaxDynamicSharedMemorySize, GEMM_SMEM);

    tab_kernel<<<kT / 256, 256>>>(Wb1, bb1, Wb2, bb2, Wb3, bb3);
    wcvt_kernel<<<512, 256>>>(Wqkv, Wproj);
    ln_kernel<<<kROWS, 256>>>(hin, gamma, beta);
    // qkv (packed out, Q pre-scaled): grid 12x32 = 384 CTAs, 3/SM = 444 slots -> single wave
    gemm_h<true><<<dim3(768 / 64, kROWS / 128), 256, GEMM_SMEM>>>(
        (const u32*)p_xh, (const u32*)p_xl, 128,
        (const u32*)p_wqh, (const u32*)p_wql, 384,
        bqkv, nullptr, nullptr, (u32*)p_qh, (u32*)p_ql, 768, 256);
    attn_kernel<<<dim3(kN / 128, kNH, kB), 256, ATTN_SMEM>>>(coord, mask);
    // out = h + ao @ Wproj + bproj
    gemm_h<false><<<dim3(256 / 64, kROWS / 128), 256, GEMM_SMEM>>>(
        (const u32*)p_aoh, (const u32*)p_aol, 128,
        (const u32*)p_wph, (const u32*)p_wpl, 128,
        bproj, hin, out, nullptr, nullptr, 256, 256);
}

// round 17
// speedup vs baseline: 1.0774x; 1.0410x over previous
#include <cuda_runtime.h>
#include <cuda_bf16.h>
#include <math.h>
#include <stdint.h>

typedef unsigned long long u64;
typedef uint32_t u32;

constexpr int kB = 4, kN = 1024, kNH = 8, kHID = 256;
constexpr int kROWS = kB * kN;
constexpr int kT = 2048;

// ---- attn smem layout (bytes), K/V/ck/mk double-buffered ----
constexpr int SO_CK  = 16384;              // 2 x 256
constexpr int SO_MK  = 16896;              // 2 x 256
constexpr int SO_QHI = 17408, SO_QLO = 27648;              // 10240 each
constexpr int SO_KHI = 37888, SO_KLO = 48128;              // 2 x 5120 each
constexpr int SO_VHI = 58368, SO_VLO = 68608;
constexpr int ATTN_SMEM = 78848;

// ---- gemm smem layout (bytes), double-buffered ----
constexpr int GO_AH = 0, GO_AL = 20480;    // 2 x 10240 each
constexpr int GO_WH = 40960, GO_WL = 50176; // 2 x 4608 each
constexpr int GEMM_SMEM = 59392;

// ---- packed bf16 hi/lo scratch (u32 = 2 bf16) ----
__device__ u32 g_xh  [kROWS * 128], g_xl  [kROWS * 128];   // LN output
__device__ u32 g_qkvh[kROWS * 384], g_qkvl[kROWS * 384];   // qkv (q pre-scaled)
__device__ u32 g_wqh [256 * 384],   g_wql [256 * 384];     // Wqkv
__device__ u32 g_wph [256 * 128],   g_wpl [256 * 128];     // Wproj
__device__ u32 g_aoh [kROWS * 128], g_aol [kROWS * 128];   // attention output
__device__ float g_tab[kNH * kT];                          // head-major, log2e pre-scaled

// ---------------- helpers ----------------
__device__ __forceinline__ u32 smem_u32(const void* p) {
    u32 a;
    asm("{ .reg .u64 t; cvta.to.shared.u64 t, %1; cvt.u32.u64 %0, t; }" : "=r"(a) : "l"(p));
    return a;
}
__device__ __forceinline__ void cp16(u32 dst, const void* src) {
    asm volatile("cp.async.cg.shared.global [%0], [%1], 16;" :: "r"(dst), "l"(src));
}
#define CP_COMMIT() asm volatile("cp.async.commit_group;" ::: "memory")
#define CP_WAIT(n)  asm volatile("cp.async.wait_group %0;" :: "n"(n) : "memory")
__device__ __forceinline__ void ldsm_x4(u32* r, u32 a) {
    asm volatile("ldmatrix.sync.aligned.m8n8.x4.shared.b16 {%0,%1,%2,%3}, [%4];"
        : "=r"(r[0]), "=r"(r[1]), "=r"(r[2]), "=r"(r[3]) : "r"(a));
}
__device__ __forceinline__ void ldsm_x4_t(u32* r, u32 a) {
    asm volatile("ldmatrix.sync.aligned.m8n8.x4.trans.shared.b16 {%0,%1,%2,%3}, [%4];"
        : "=r"(r[0]), "=r"(r[1]), "=r"(r[2]), "=r"(r[3]) : "r"(a));
}
__device__ __forceinline__ void mma_bf16(float* d, const u32* a, u32 b0, u32 b1) {
    asm volatile(
        "mma.sync.aligned.m16n8k16.row.col.f32.bf16.bf16.f32 "
        "{%0,%1,%2,%3}, {%4,%5,%6,%7}, {%8,%9}, {%0,%1,%2,%3};"
        : "+f"(d[0]), "+f"(d[1]), "+f"(d[2]), "+f"(d[3])
        : "r"(a[0]), "r"(a[1]), "r"(a[2]), "r"(a[3]), "r"(b0), "r"(b1));
}
__device__ __forceinline__ float ex2(float x) {
    float y; asm("ex2.approx.f32 %0, %1;" : "=f"(y) : "f"(x)); return y;
}
__device__ __forceinline__ u32 pk2(float a, float b) {
    __nv_bfloat162 t = __floats2bfloat162_rn(a, b);
    return *reinterpret_cast<u32*>(&t);
}
__device__ __forceinline__ float lo_f(u32 h) { return __uint_as_float(h << 16); }
__device__ __forceinline__ float hi_f(u32 h) { return __uint_as_float(h & 0xffff0000u); }

// ---------------- LayerNorm -> packed hi/lo ----------------
__global__ void ln_kernel(const float* __restrict__ hin, const float* __restrict__ gamma,
                          const float* __restrict__ beta)
{
    __shared__ float red[16];
    int row = blockIdx.x, t = threadIdx.x;
    float x = hin[(size_t)row * kHID + t];
    float s = x, s2 = x * x;
    #pragma unroll
    for (int off = 16; off; off >>= 1) {
        s  += __shfl_xor_sync(0xffffffffu, s,  off);
        s2 += __shfl_xor_sync(0xffffffffu, s2, off);
    }
    if ((t & 31) == 0) { red[t >> 5] = s; red[8 + (t >> 5)] = s2; }
    __syncthreads();
    float sum = 0.f, sum2 = 0.f;
    #pragma unroll
    for (int i = 0; i < 8; i++) { sum += red[i]; sum2 += red[8 + i]; }
    float mu = sum * (1.f / 256.f);
    float var = sum2 * (1.f / 256.f) - mu * mu;
    float r = rsqrtf(var + 1e-5f);
    float val = (x - mu) * r * gamma[t] + beta[t];
    float vn = __shfl_xor_sync(0xffffffffu, val, 1);
    if (!(t & 1)) {
        u32 hh = pk2(val, vn);
        u32 ll = pk2(val - lo_f(hh), vn - hi_f(hh));
        g_xh[(size_t)row * 128 + (t >> 1)] = hh;
        g_xl[(size_t)row * 128 + (t >> 1)] = ll;
    }
}

// ---------------- weight pre-split ----------------
__global__ void __launch_bounds__(256) wcvt_kernel(
    const float* __restrict__ Wqkv, const float* __restrict__ Wproj)
{
    int i = blockIdx.x * 256 + threadIdx.x;
    if (i < 256 * 384) {
        float a = Wqkv[2 * i], b = Wqkv[2 * i + 1];
        u32 hh = pk2(a, b);
        g_wqh[i] = hh;
        g_wql[i] = pk2(a - lo_f(hh), b - hi_f(hh));
    } else {
        int j = i - 256 * 384;
        if (j < 256 * 128) {
            float a = Wproj[2 * j], b = Wproj[2 * j + 1];
            u32 hh = pk2(a, b);
            g_wph[j] = hh;
            g_wpl[j] = pk2(a - lo_f(hh), b - hi_f(hh));
        }
    }
}

// ---------------- bias table ----------------
__global__ void __launch_bounds__(256) tab_kernel(
    const float* __restrict__ Wb1, const float* __restrict__ bb1,
    const float* __restrict__ Wb2, const float* __restrict__ bb2,
    const float* __restrict__ Wb3, const float* __restrict__ bb3)
{
    __shared__ float w1[64], c1[64], w2[4096], c2[64], w3[512], c3[8];
    int t = threadIdx.x;
    if (t < 64) { w1[t] = Wb1[t]; c1[t] = bb1[t]; c2[t] = bb2[t]; }
    if (t < 8)  c3[t] = bb3[t];
    for (int i = t; i < 4096; i += 256) w2[i] = Wb2[i];
    for (int i = t; i < 512;  i += 256) w3[i] = Wb3[i];
    __syncthreads();
    int idx = blockIdx.x * 256 + t;
    float d = -1.f + 2.f * (float)idx / (float)(kT - 1);
    float h1[64];
    #pragma unroll
    for (int u = 0; u < 64; u++) {
        float a = fmaf(d, w1[u], c1[u]);
        h1[u] = a / (1.f + expf(-a));
    }
    float acc[8];
    #pragma unroll
    for (int m = 0; m < 8; m++) acc[m] = c3[m];
    for (int u2 = 0; u2 < 64; u2++) {
        float a = c2[u2];
        #pragma unroll
        for (int u = 0; u < 64; u++) a = fmaf(h1[u], w2[u * 64 + u2], a);
        float sv = a / (1.f + expf(-a));
        #pragma unroll
        for (int m = 0; m < 8; m++) acc[m] = fmaf(sv, w3[u2 * 8 + m], acc[m]);
    }
    #pragma unroll
    for (int m = 0; m < 8; m++) g_tab[m * kT + idx] = acc[m] * 1.4426950408889634f;
}

// ---------------- HMMA GEMM, cp.async double-buffered, 1 sync/chunk ----------------
template<bool PACKED_OUT>
__global__ void __launch_bounds__(256, 3) gemm_h(
    const u32* __restrict__ Ah, const u32* __restrict__ Al, int aStr,
    const u32* __restrict__ Wh, const u32* __restrict__ Wl, int wStr,
    const float* __restrict__ bias, const float* __restrict__ resid,
    float* __restrict__ C, u32* __restrict__ outH, u32* __restrict__ outL,
    int N, int K)
{
    extern __shared__ char smg[];
    const u32 smb = smem_u32(smg);

    const int n0 = blockIdx.x * 64, m0 = blockIdx.y * 128;
    const int t = threadIdx.x, w = t >> 5, lane = t & 31;
    const int r1 = lane >> 2;
    const int KC = K / 32;

    auto stage = [&](int c, int bb) {
        int k0 = c * 32;
        #pragma unroll
        for (int i = 0; i < 2; i++) {
            int idx = t + i * 256;
            int row = idx >> 2, q4 = idx & 3;
            size_t src = (size_t)(m0 + row) * aStr + (k0 >> 1) + q4 * 4;
            u32 doff = bb * 10240 + row * 80 + q4 * 16;
            cp16(smb + GO_AH + doff, Ah + src);
            cp16(smb + GO_AL + doff, Al + src);
        }
        {
            int row = t >> 3, q4 = t & 7;
            size_t src = (size_t)(k0 + row) * wStr + (n0 >> 1) + q4 * 4;
            u32 doff = bb * 4608 + row * 144 + q4 * 16;
            cp16(smb + GO_WH + doff, Wh + src);
            cp16(smb + GO_WL + doff, Wl + src);
        }
    };

    float o[8][4] = {};

    stage(0, 0);
    CP_COMMIT();

    for (int c = 0; c < KC; c++) {
        int bb = c & 1;
        CP_WAIT(0);            // group for buffer bb has landed
        __syncthreads();       // publish + prior readers of bb^1 done
        if (c + 1 < KC) { stage(c + 1, bb ^ 1); CP_COMMIT(); }

        u32 abase = smb + GO_AH + bb * 10240;
        u32 wbase = smb + GO_WH + bb * 4608;
        #pragma unroll
        for (int ks = 0; ks < 2; ks++) {
            u32 aAh[4], aAl[4];
            u32 qa = abase + (16 * w + (lane & 15)) * 80 + ks * 32 + ((lane >> 4) << 4);
            ldsm_x4(aAh, qa);
            ldsm_x4(aAl, qa + (GO_AL - GO_AH));
            #pragma unroll
            for (int nb = 0; nb < 4; nb++) {
                u32 whf[4], wlf[4];
                u32 wa = wbase + (ks * 16 + (lane & 15)) * 144 + nb * 32 + ((lane >> 4) << 4);
                ldsm_x4_t(whf, wa);
                ldsm_x4_t(wlf, wa + (GO_WL - GO_WH));
                mma_bf16(o[2 * nb],     aAh, whf[0], whf[1]);
                mma_bf16(o[2 * nb + 1], aAh, whf[2], whf[3]);
                mma_bf16(o[2 * nb],     aAl, whf[0], whf[1]);
                mma_bf16(o[2 * nb + 1], aAl, whf[2], whf[3]);
                mma_bf16(o[2 * nb],     aAh, wlf[0], wlf[1]);
                mma_bf16(o[2 * nb + 1], aAh, wlf[2], wlf[3]);
            }
        }
    }

    const float QSCALE = 1.4426950408889634f / 5.656854249492381f;
    int row1 = m0 + 16 * w + r1;
    #pragma unroll
    for (int nb2 = 0; nb2 < 8; nb2++) {
        int col = n0 + nb2 * 8 + 2 * (lane & 3);
        float b0 = bias[col], b1 = bias[col + 1];
        float v00 = o[nb2][0] + b0, v01 = o[nb2][1] + b1;
        float v10 = o[nb2][2] + b0, v11 = o[nb2][3] + b1;
        if (PACKED_OUT) {
            float sc = (col < 256) ? QSCALE : 1.f;
            v00 *= sc; v01 *= sc; v10 *= sc; v11 *= sc;
            u32 h0 = pk2(v00, v01), h1 = pk2(v10, v11);
            u32 l0 = pk2(v00 - lo_f(h0), v01 - hi_f(h0));
            u32 l1 = pk2(v10 - lo_f(h1), v11 - hi_f(h1));
            size_t o0 = (size_t)row1 * (N >> 1) + (col >> 1);
            size_t o1 = (size_t)(row1 + 8) * (N >> 1) + (col >> 1);
            outH[o0] = h0; outL[o0] = l0;
            outH[o1] = h1; outL[o1] = l1;
        } else {
            v00 += resid[(size_t)row1 * N + col];
            v01 += resid[(size_t)row1 * N + col + 1];
            v10 += resid[(size_t)(row1 + 8) * N + col];
            v11 += resid[(size_t)(row1 + 8) * N + col + 1];
            *(float2*)(C + (size_t)row1 * N + col)       = make_float2(v00, v01);
            *(float2*)(C + (size_t)(row1 + 8) * N + col) = make_float2(v10, v11);
        }
    }
}

// ---------------- HMMA flash attention, fixed-base softmax (no online max) ----------------
// s in [-~20, ~20] (see analysis) => exp2(s) is exact softmax up to fp32 rounding.
__global__ void __launch_bounds__(256, 2) attn_kernel(
    const float* __restrict__ coord, const int* __restrict__ mask)
{
    extern __shared__ char smc[];
    float2* TB2 = (float2*)smc;
    const u32 smb = smem_u32(smc);

    const int qt = blockIdx.x, h = blockIdx.y, b = blockIdx.z;
    const int q0 = qt * 128;
    const int t = threadIdx.x, w = t >> 5, lane = t & 31;

    auto prefetch = [&](int tile, int bb) {
        int j0 = tile * 64;
        int row = t >> 2, q4 = t & 3;
        size_t base = (size_t)(b * kN + j0 + row) * 384 + h * 16 + q4 * 4;
        u32 doff = bb * 5120 + row * 80 + q4 * 16;
        cp16(smb + SO_KHI + doff, g_qkvh + base + 128);
        cp16(smb + SO_KLO + doff, g_qkvl + base + 128);
        cp16(smb + SO_VHI + doff, g_qkvh + base + 256);
        cp16(smb + SO_VLO + doff, g_qkvl + base + 256);
        if (t < 16)      cp16(smb + SO_CK + bb * 256 + t * 16, coord + b * kN + j0 + t * 4);
        else if (t < 32) cp16(smb + SO_MK + bb * 256 + (t - 16) * 16, mask + b * kN + j0 + (t - 16) * 4);
    };

    prefetch(0, 0);
    CP_COMMIT();

    #pragma unroll
    for (int i = 0; i < 8; i++) {
        int idx = t + i * 256;
        float f0 = g_tab[h * kT + idx];
        float f1 = g_tab[h * kT + (idx < kT - 1 ? idx + 1 : kT - 1)];
        TB2[idx] = make_float2(f0, f1);
    }
    #pragma unroll
    for (int i = 0; i < 2; i++) {
        int idx = t + i * 256;
        int row = idx >> 2, q4 = idx & 3;
        size_t src = (size_t)(b * kN + q0 + row) * 384 + h * 16 + q4 * 4;
        *(uint4*)(smc + SO_QHI + row * 80 + q4 * 16) = *(const uint4*)(g_qkvh + src);
        *(uint4*)(smc + SO_QLO + row * 80 + q4 * 16) = *(const uint4*)(g_qkvl + src);
    }
    __syncthreads();

    u32 aQh[2][4], aQl[2][4];
    {
        u32 qa = smb + SO_QHI + (16 * w + (lane & 15)) * 80 + ((lane >> 4) << 4);
        ldsm_x4(aQh[0], qa);
        ldsm_x4(aQh[1], qa + 32);
        ldsm_x4(aQl[0], qa + (SO_QLO - SO_QHI));
        ldsm_x4(aQl[1], qa + (SO_QLO - SO_QHI) + 32);
    }

    const int r1 = lane >> 2;
    const float cq1 = coord[b * kN + q0 + 16 * w + r1];
    const float cq2 = coord[b * kN + q0 + 16 * w + r1 + 8];
    const float aq1 = fmaf(-cq1, 1023.5f, 1023.5f);
    const float aq2 = fmaf(-cq2, 1023.5f, 1023.5f);

    float l1 = 0.f, l2 = 0.f;
    float o[4][4] = {};

    for (int tile = 0; tile < 16; tile++) {
        const int cur = tile & 1;
        CP_WAIT(0);
        __syncthreads();
        if (tile + 1 < 16) { prefetch(tile + 1, cur ^ 1); CP_COMMIT(); }

        const float* ck = (const float*)(smc + SO_CK + cur * 256);
        const int*  mkp = (const int*)  (smc + SO_MK + cur * 256);
        const u32 kbase = smb + SO_KHI + cur * 5120;
        const u32 vbase = smb + SO_VHI + cur * 5120;

        // ---- S = Q K^T ----
        float sacc[8][4];
        #pragma unroll
        for (int i = 0; i < 8; i++)
            { sacc[i][0] = 0.f; sacc[i][1] = 0.f; sacc[i][2] = 0.f; sacc[i][3] = 0.f; }
        #pragma unroll
        for (int ks = 0; ks < 2; ks++) {
            #pragma unroll
            for (int nb = 0; nb < 4; nb++) {
                u32 kh[4], kl[4];
                u32 ka = kbase + (nb * 16 + (lane & 15)) * 80 + ks * 32 + ((lane >> 4) << 4);
                ldsm_x4(kh, ka);
                ldsm_x4(kl, ka + (SO_KLO - SO_KHI));
                mma_bf16(sacc[2 * nb],     aQh[ks], kh[0], kh[2]);
                mma_bf16(sacc[2 * nb + 1], aQh[ks], kh[1], kh[3]);
                mma_bf16(sacc[2 * nb],     aQl[ks], kh[0], kh[2]);
                mma_bf16(sacc[2 * nb + 1], aQl[ks], kh[1], kh[3]);
                mma_bf16(sacc[2 * nb],     aQh[ks], kl[0], kl[2]);
                mma_bf16(sacc[2 * nb + 1], aQh[ks], kl[1], kl[3]);
            }
        }

        // ---- fused softmax: p = exp2(s + bias), accumulate l, pack P ----
        float su1 = 0.f, su2 = 0.f;
        u32 phi[16];
        #pragma unroll
        for (int cb = 0; cb < 8; cb++) {
            int c0 = cb * 8 + 2 * (lane & 3);
            float ck0 = ck[c0], ck1 = ck[c0 + 1];
            int mk0 = mkp[c0], mk1 = mkp[c0 + 1];
            float u00 = fmaf(ck0, 1023.5f, aq1), u01 = fmaf(ck1, 1023.5f, aq1);
            float u10 = fmaf(ck0, 1023.5f, aq2), u11 = fmaf(ck1, 1023.5f, aq2);
            int i00 = (int)u00, i01 = (int)u01, i10 = (int)u10, i11 = (int)u11;
            float2 t00 = TB2[i00], t01 = TB2[i01], t10 = TB2[i10], t11 = TB2[i11];
            float s00 = sacc[cb][0] + fmaf(u00 - (float)i00, t00.y - t00.x, t00.x);
            float s01 = sacc[cb][1] + fmaf(u01 - (float)i01, t01.y - t01.x, t01.x);
            float s10 = sacc[cb][2] + fmaf(u10 - (float)i10, t10.y - t10.x, t10.x);
            float s11 = sacc[cb][3] + fmaf(u11 - (float)i11, t11.y - t11.x, t11.x);
            if (!mk0) { s00 = -1e38f; s10 = -1e38f; }
            if (!mk1) { s01 = -1e38f; s11 = -1e38f; }
            float p00 = ex2(s00), p01 = ex2(s01);
            float p10 = ex2(s10), p11 = ex2(s11);
            su1 += p00 + p01; su2 += p10 + p11;
            phi[2 * cb]     = pk2(p00, p01);
            phi[2 * cb + 1] = pk2(p10, p11);
        }
        l1 += su1;   // quad-partial; reduced once at end
        l2 += su2;

        // ---- O += P V  (Phi·Vhi + Phi·Vlo) ----
        #pragma unroll
        for (int kc = 0; kc < 4; kc++) {
            #pragma unroll
            for (int dp = 0; dp < 2; dp++) {
                u32 vh[4], vl[4];
                u32 va = vbase + (16 * kc + (lane & 15)) * 80 + dp * 32 + ((lane >> 4) << 4);
                ldsm_x4_t(vh, va);
                ldsm_x4_t(vl, va + (SO_VLO - SO_VHI));
                mma_bf16(o[2 * dp],     &phi[4 * kc], vh[0], vh[1]);
                mma_bf16(o[2 * dp + 1], &phi[4 * kc], vh[2], vh[3]);
                mma_bf16(o[2 * dp],     &phi[4 * kc], vl[0], vl[1]);
                mma_bf16(o[2 * dp + 1], &phi[4 * kc], vl[2], vl[3]);
            }
        }
    }

    // reduce quad-partial denominators to full-row sums
    l1 += __shfl_xor_sync(0xffffffffu, l1, 1);
    l1 += __shfl_xor_sync(0xffffffffu, l1, 2);
    l2 += __shfl_xor_sync(0xffffffffu, l2, 1);
    l2 += __shfl_xor_sync(0xffffffffu, l2, 2);

    float inv1 = 1.f / l1, inv2 = 1.f / l2;
    int row1 = b * kN + q0 + 16 * w + r1;
    #pragma unroll
    for (int db = 0; db < 4; db++) {
        int c = h * 32 + db * 8 + 2 * (lane & 3);
        float v00 = o[db][0] * inv1, v01 = o[db][1] * inv1;
        float v10 = o[db][2] * inv2, v11 = o[db][3] * inv2;
        u32 h0 = pk2(v00, v01), h1 = pk2(v10, v11);
        u32 l0 = pk2(v00 - lo_f(h0), v01 - hi_f(h0));
        u32 l1p = pk2(v10 - lo_f(h1), v11 - hi_f(h1));
        g_aoh[(size_t)row1 * 128 + (c >> 1)] = h0;
        g_aol[(size_t)row1 * 128 + (c >> 1)] = l0;
        g_aoh[(size_t)(row1 + 8) * 128 + (c >> 1)] = h1;
        g_aol[(size_t)(row1 + 8) * 128 + (c >> 1)] = l1p;
    }
}

// ---------------- launch ----------------
extern "C" void kernel_launch(void* const* d_in, const int* in_sizes, int n_in,
                              void* d_out, int out_size)
{
    const float* hin   = (const float*)d_in[0];
    const float* coord = (const float*)d_in[1];
    const int*   mask  = (const int*)  d_in[2];
    const float* Wqkv  = (const float*)d_in[3];
    const float* bqkv  = (const float*)d_in[4];
    const float* Wproj = (const float*)d_in[5];
    const float* bproj = (const float*)d_in[6];
    const float* gamma = (const float*)d_in[7];
    const float* beta  = (const float*)d_in[8];
    const float* Wb1 = (const float*)d_in[9],  *bb1 = (const float*)d_in[10];
    const float* Wb2 = (const float*)d_in[11], *bb2 = (const float*)d_in[12];
    const float* Wb3 = (const float*)d_in[13], *bb3 = (const float*)d_in[14];
    float* out = (float*)d_out;

    void *p_xh, *p_xl, *p_qh, *p_ql, *p_wqh, *p_wql, *p_wph, *p_wpl, *p_aoh, *p_aol;
    cudaGetSymbolAddress(&p_xh, g_xh);   cudaGetSymbolAddress(&p_xl, g_xl);
    cudaGetSymbolAddress(&p_qh, g_qkvh); cudaGetSymbolAddress(&p_ql, g_qkvl);
    cudaGetSymbolAddress(&p_wqh, g_wqh); cudaGetSymbolAddress(&p_wql, g_wql);
    cudaGetSymbolAddress(&p_wph, g_wph); cudaGetSymbolAddress(&p_wpl, g_wpl);
    cudaGetSymbolAddress(&p_aoh, g_aoh); cudaGetSymbolAddress(&p_aol, g_aol);

    cudaFuncSetAttribute(attn_kernel, cudaFuncAttributeMaxDynamicSharedMemorySize, ATTN_SMEM);
    cudaFuncSetAttribute(gemm_h<true>,  cudaFuncAttributeMaxDynamicSharedMemorySize, GEMM_SMEM);
    cudaFuncSetAttribute(gemm_h<false>, cudaFuncAttributeMaxDynamicSharedMemorySize, GEMM_SMEM);

    tab_kernel<<<kT / 256, 256>>>(Wb1, bb1, Wb2, bb2, Wb3, bb3);
    wcvt_kernel<<<512, 256>>>(Wqkv, Wproj);
    ln_kernel<<<kROWS, 256>>>(hin, gamma, beta);
    // qkv (packed out, Q pre-scaled)
    gemm_h<true><<<dim3(768 / 64, kROWS / 128), 256, GEMM_SMEM>>>(
        (const u32*)p_xh, (const u32*)p_xl, 128,
        (const u32*)p_wqh, (const u32*)p_wql, 384,
        bqkv, nullptr, nullptr, (u32*)p_qh, (u32*)p_ql, 768, 256);
    attn_kernel<<<dim3(kN / 128, kNH, kB), 256, ATTN_SMEM>>>(coord, mask);
    // out = h + ao @ Wproj + bproj
    gemm_h<false><<<dim3(256 / 64, kROWS / 128), 256, GEMM_SMEM>>>(
        (const u32*)p_aoh, (const u32*)p_aol, 128,
        (const u32*)p_wph, (const u32*)p_wpl, 128,
        bproj, hin, out, nullptr, nullptr, 256, 256);
}